// round 11
// baseline (speedup 1.0000x reference)
#include <cuda_runtime.h>
#include <cuda_bf16.h>
#include <cstdint>

typedef unsigned int u32; typedef unsigned short u16;

// AttentionMV B=T=1024, E=128. mma.sync bf16 3-pass split. R11: 512 threads.
//  Warp (g = w>>3, wl = w&7):
//  GEMM1: d1[f=wl*16..+15][t = g*32..+31 of tile] = sum_e WT[f][e]*m[t][e]
//  u = tanh(d1+b) -> bf16 hi/lo -> UF smem (B-frag layout, lane==lane)
//  GEMM2: pre[e=g*64..+63][f=wl*16..+15] += sum_t vT[e][t]*u[t][f] (full t)
//  pre fully partitioned across warps; softmax epilogue as before.

constexpr int NT = 512;
constexpr u32 WFH=0, WFL=32768;           // W frags 64KB
constexpr u32 MFH=65536, MFL=81920;       // m frags 32KB
constexpr u32 UFH=98304, UFL=114688;      // u frags 32KB
constexpr u32 MRAW=131072;                // raw m tile 32KB (cp.async target)
constexpr u32 P_OFF=0, EX_OFF=98304;      // epilogue aliases (dead regions)
constexpr u32 SP_OFF=165888;              // 16*128 f32 colsum partials
constexpr u32 CF_OFF=174080;              // 128 f32
constexpr u32 SMEM_BYTES=174592;

__device__ u16 g_vtFH[131072];   // vT A-frag images, 16KB per 64-t tile
__device__ u16 g_vtFL[131072];

__device__ __forceinline__ float fast_tanh(float x){
    float e = __expf(2.0f*x);
    return 1.0f - __fdividef(2.0f, e+1.0f);
}
__device__ __forceinline__ float trunc_hi(float x){
    return __uint_as_float(__float_as_uint(x) & 0xffff0000u);
}
__device__ __forceinline__ u32 cvt_bf16x2(float hiArg, float loArg){
    u32 d; asm("cvt.rn.bf16x2.f32 %0, %1, %2;" : "=r"(d) : "f"(hiArg), "f"(loArg));
    return d;
}
__device__ __forceinline__ void mma16816(float* d, u32 a0,u32 a1,u32 a2,u32 a3,
                                         u32 b0,u32 b1){
    asm volatile("mma.sync.aligned.m16n8k16.row.col.f32.bf16.bf16.f32 "
        "{%0,%1,%2,%3}, {%4,%5,%6,%7}, {%8,%9}, {%0,%1,%2,%3};"
        : "+f"(d[0]),"+f"(d[1]),"+f"(d[2]),"+f"(d[3])
        : "r"(a0),"r"(a1),"r"(a2),"r"(a3),"r"(b0),"r"(b1));
}
__device__ __forceinline__ u32 smem_u32(const void* p){
    u32 a; asm("{ .reg .u64 t; cvta.to.shared.u64 t, %1; cvt.u32.u64 %0, t; }"
               : "=r"(a) : "l"(p));
    return a;
}
__device__ __forceinline__ void cp16(u32 dst, const void* src){
    asm volatile("cp.async.ca.shared.global [%0], [%1], 16;" :: "r"(dst), "l"(src));
}

// vT A-frag prep: a-frag for A[m=e][k=t] (same as R9/R10)
__global__ void vt_prep(const float* __restrict__ gv){
    int t = blockIdx.x, e = threadIdx.x;
    float x = gv[t*128 + e];
    u16 hi = (u16)(__float_as_uint(x) >> 16);
    u16 lo = __bfloat16_as_ushort(__float2bfloat16(x - trunc_hi(x)));
    int tile = t>>6, s = (t>>4)&3, tr = t&15;
    int kh = tr>>3, rs = (tr&7)>>1, byt = tr&1;
    int i = e>>4, eq = e&15, rh = eq>>3, q = eq&7;
    int reg = rh + 2*kh, lane = q*4 + rs;
    int idx = ((tile*32 + i*4 + s)*32 + lane)*8 + reg*2 + byt;
    g_vtFH[idx] = hi; g_vtFL[idx] = lo;
}

__global__ __launch_bounds__(NT,1)
void attn_mma(const float* __restrict__ gm, const float* __restrict__ gW,
              const float* __restrict__ gb, float* __restrict__ gout)
{
    extern __shared__ char sm[];
    const u32 sbase = smem_u32(sm);
    const int tid=threadIdx.x, lane=tid&31, w=tid>>5, bb=blockIdx.x;
    const int g=w>>3, wl=w&7;
    const int q=lane>>2, r2=(lane&3)*2;
    const float* Wb = gW + (size_t)bb*16384;
    const char*  mbc = (const char*)(gm + (size_t)bb*131072);

    // ---- prologue: start streaming m tile 0 into MRAW
    #pragma unroll
    for (int k2=0;k2<4;k2++)
        cp16(sbase + MRAW + tid*64 + k2*16, mbc + tid*64 + k2*16);
    asm volatile("cp.async.commit_group;");

    // ---- W -> A-frag layout (hi/lo)
    for (int it=0; it<32; it++){
        int idx = it*NT + tid;
        int e = idx>>7, f = idx&127;
        float x = __ldg(Wb + idx);
        u16 hi = (u16)(__float_as_uint(x) >> 16);
        u16 lo = __bfloat16_as_ushort(__float2bfloat16(x - trunc_hi(x)));
        int w2=f>>4, fr=f&15, rh=fr>>3, qq=fr&7;
        int ks=e>>4, er=e&15, kh=er>>3, rs=(er&7)>>1, byt=er&1;
        u32 off = (u32)(((w2*8+ks)*32 + qq*4 + rs)*16 + (rh + 2*kh)*4 + byt*2);
        *(u16*)(sm + WFH + off) = hi;
        *(u16*)(sm + WFL + off) = lo;
    }

    float pre[4][2][4];
    #pragma unroll
    for (int i=0;i<4;i++)
        #pragma unroll
        for (int fb=0;fb<2;fb++)
            #pragma unroll
            for (int j=0;j<4;j++) pre[i][fb][j]=0.f;
    float s4[4]={0,0,0,0};
    const int f0 = wl*16 + q;

    for (int tile=0; tile<16; tile++){
        // ---- m(tile) landed; visible to all
        asm volatile("cp.async.wait_group 0;");
        __syncthreads();                                   // S1

        // ---- msplit: thread handles rows t=w*4+j, e=lane*4..+3
        #pragma unroll
        for (int j=0;j<4;j++){
            int t = w*4 + j;
            float4 x = *(const float4*)(sm + MRAW + (u32)(t*32+lane)*16);
            s4[0]+=x.x; s4[1]+=x.y; s4[2]+=x.z; s4[3]+=x.w;
            u32 hA = __byte_perm(__float_as_uint(x.x), __float_as_uint(x.y), 0x7632);
            u32 hB = __byte_perm(__float_as_uint(x.z), __float_as_uint(x.w), 0x7632);
            float l0 = x.x - trunc_hi(x.x), l1 = x.y - trunc_hi(x.y);
            float l2 = x.z - trunc_hi(x.z), l3 = x.w - trunc_hi(x.w);
            u32 lA = cvt_bf16x2(l1, l0), lB = cvt_bf16x2(l3, l2);
            int nbg = t>>3, n = t&7;
            int lp = n*4 + (lane&1)*2, r = (lane>>1)&1, ks = lane>>2;
            u32 blk = (u32)(nbg*8+ks)*256;
            u32 iA = (u32)((lp*2     + r + ks*8) & 63)*4;
            u32 iB = (u32)(((lp+1)*2 + r + ks*8) & 63)*4;
            *(u32*)(sm + MFH + blk + iA) = hA;
            *(u32*)(sm + MFH + blk + iB) = hB;
            *(u32*)(sm + MFL + blk + iA) = lA;
            *(u32*)(sm + MFL + blk + iB) = lB;
        }
        __syncthreads();                                   // S2: MF ready, MRAW free

        // ---- stream m(tile+1)
        if (tile < 15){
            const char* src = mbc + (size_t)(tile+1)*32768;
            #pragma unroll
            for (int k2=0;k2<4;k2++)
                cp16(sbase + MRAW + tid*64 + k2*16, src + tid*64 + k2*16);
        }
        asm volatile("cp.async.commit_group;");

        // ---- bias prefetch
        float bv[16];
        #pragma unroll
        for (int nb=0;nb<4;nb++){
            const float* bp = gb + (size_t)(tile*64 + (g*4+nb)*8 + r2)*128;
            bv[nb*4+0]=__ldg(bp+f0);     bv[nb*4+1]=__ldg(bp+128+f0);
            bv[nb*4+2]=__ldg(bp+f0+8);   bv[nb*4+3]=__ldg(bp+128+f0+8);
        }

        // ---- GEMM1: warp (g,wl): f rows wl*16..+15, t cols g*32..+31
        float d1[4][4];
        #pragma unroll
        for (int nb=0;nb<4;nb++){ d1[nb][0]=0;d1[nb][1]=0;d1[nb][2]=0;d1[nb][3]=0; }
        #pragma unroll
        for (int ks=0;ks<8;ks++){
            uint4 ahv = *(const uint4*)(sm + WFH + (u32)(((wl*8+ks)*32+lane)*16));
            uint4 alv = *(const uint4*)(sm + WFL + (u32)(((wl*8+ks)*32+lane)*16));
            u32 bh[4][2], blo[4][2];
            u32 bpos = (u32)(((lane*2) + ks*8) & 63)*4;
            #pragma unroll
            for (int nb=0;nb<4;nb++){
                int nbg = g*4+nb;
                uint2 t2 = *(const uint2*)(sm + MFH + (u32)(nbg*8+ks)*256 + bpos);
                bh[nb][0]=t2.x; bh[nb][1]=t2.y;
                uint2 t3 = *(const uint2*)(sm + MFL + (u32)(nbg*8+ks)*256 + bpos);
                blo[nb][0]=t3.x; blo[nb][1]=t3.y;
            }
            #pragma unroll
            for (int nb=0;nb<4;nb++)
                mma16816(d1[nb], ahv.x,ahv.y,ahv.z,ahv.w, bh[nb][0],bh[nb][1]);
            #pragma unroll
            for (int nb=0;nb<4;nb++)
                mma16816(d1[nb], ahv.x,ahv.y,ahv.z,ahv.w, blo[nb][0],blo[nb][1]);
            #pragma unroll
            for (int nb=0;nb<4;nb++)
                mma16816(d1[nb], alv.x,alv.y,alv.z,alv.w, bh[nb][0],bh[nb][1]);
        }

        // ---- bias + tanh + split; store u frags (writer lane == reader lane)
        u32 uh[4][2], ul[4][2];
        #pragma unroll
        for (int nb=0;nb<4;nb++){
            float u0=fast_tanh(d1[nb][0]+bv[nb*4+0]);
            float u1=fast_tanh(d1[nb][1]+bv[nb*4+1]);
            float u2=fast_tanh(d1[nb][2]+bv[nb*4+2]);
            float u3=fast_tanh(d1[nb][3]+bv[nb*4+3]);
            uh[nb][0] = __byte_perm(__float_as_uint(u0), __float_as_uint(u1), 0x7632);
            uh[nb][1] = __byte_perm(__float_as_uint(u2), __float_as_uint(u3), 0x7632);
            ul[nb][0] = cvt_bf16x2(u1 - trunc_hi(u1), u0 - trunc_hi(u0));
            ul[nb][1] = cvt_bf16x2(u3 - trunc_hi(u3), u2 - trunc_hi(u2));
        }
        #pragma unroll
        for (int k2=0;k2<2;k2++){
            int s_blk = g*2 + k2;
            #pragma unroll
            for (int fbi=0;fbi<2;fbi++){
                u32 off = (u32)(s_blk*16 + wl*2+fbi)*256 + lane*8;
                *(uint2*)(sm + UFH + off) = make_uint2(uh[2*k2][fbi], uh[2*k2+1][fbi]);
                *(uint2*)(sm + UFL + off) = make_uint2(ul[2*k2][fbi], ul[2*k2+1][fbi]);
            }
        }
        __syncthreads();                                   // S3: UF ready

        // ---- GEMM2: warp (g,wl): e blocks i=g*4+0..3, f=wl*16..+15, full t
        uint4 aH[2][4], aL[2][4];
        #pragma unroll
        for (int ii=0;ii<4;ii++){
            size_t a = ((size_t)((tile*32 + (g*4+ii)*4 + 0)*32 + lane))*16;
            aH[0][ii] = *(const uint4*)((const char*)g_vtFH + a);
            aL[0][ii] = *(const uint4*)((const char*)g_vtFL + a);
        }
        #pragma unroll
        for (int s=0;s<4;s++){
            const int cb = s&1;
            if (s<3){
                #pragma unroll
                for (int ii=0;ii<4;ii++){
                    size_t a = ((size_t)((tile*32 + (g*4+ii)*4 + s+1)*32 + lane))*16;
                    aH[cb^1][ii] = *(const uint4*)((const char*)g_vtFH + a);
                    aL[cb^1][ii] = *(const uint4*)((const char*)g_vtFL + a);
                }
            }
            uint2 bH[2], bL[2];
            #pragma unroll
            for (int fbi=0;fbi<2;fbi++){
                u32 off = (u32)(s*16 + wl*2+fbi)*256 + lane*8;
                bH[fbi] = *(const uint2*)(sm + UFH + off);
                bL[fbi] = *(const uint2*)(sm + UFL + off);
            }
            #pragma unroll
            for (int ii=0;ii<4;ii++)
                #pragma unroll
                for (int fbi=0;fbi<2;fbi++)
                    mma16816(pre[ii][fbi], aH[cb][ii].x,aH[cb][ii].y,aH[cb][ii].z,aH[cb][ii].w,
                             bH[fbi].x, bH[fbi].y);
            #pragma unroll
            for (int ii=0;ii<4;ii++)
                #pragma unroll
                for (int fbi=0;fbi<2;fbi++)
                    mma16816(pre[ii][fbi], aH[cb][ii].x,aH[cb][ii].y,aH[cb][ii].z,aH[cb][ii].w,
                             bL[fbi].x, bL[fbi].y);
            #pragma unroll
            for (int ii=0;ii<4;ii++)
                #pragma unroll
                for (int fbi=0;fbi<2;fbi++)
                    mma16816(pre[ii][fbi], aL[cb][ii].x,aL[cb][ii].y,aL[cb][ii].z,aL[cb][ii].w,
                             bH[fbi].x, bH[fbi].y);
        }
    }
    __syncthreads();   // all frag-region reads done before epilogue aliasing

    // ---- epilogue: pre -> P (fully partitioned, no reduction needed)
    float* P = (float*)(sm + P_OFF);
    #pragma unroll
    for (int ii=0;ii<4;ii++)
        #pragma unroll
        for (int fb=0;fb<2;fb++){
            int e0 = (g*4+ii)*16 + q, ff = wl*16 + fb*8 + r2;
            P[e0*132+ff]       = pre[ii][fb][0];
            P[e0*132+ff+1]     = pre[ii][fb][1];
            P[(e0+8)*132+ff]   = pre[ii][fb][2];
            P[(e0+8)*132+ff+1] = pre[ii][fb][3];
        }
    float* SP=(float*)(sm+SP_OFF);
    *(float4*)(SP + w*128 + lane*4) = make_float4(s4[0],s4[1],s4[2],s4[3]);
    __syncthreads();

    float* EX=(float*)(sm+EX_OFF);
    float* CF=(float*)(sm+CF_OFF);
    if (tid<128){
        int e=tid;
        float ss=0;
        #pragma unroll
        for (int ww=0;ww<16;ww++) ss+=SP[ww*128+e];
        float mx=-1e30f;
        #pragma unroll 8
        for (int f=0;f<128;f++) mx=fmaxf(mx,P[e*132+f]);
        float sum=0;
        #pragma unroll 4
        for (int f=0;f<128;f++){
            float ex=__expf(P[e*132+f]-mx);
            sum+=ex; EX[f*132+e]=ex;
        }
        CF[e]=ss*__fdividef(1.f,sum);
    }
    __syncthreads();
    if (tid<128){
        int f=tid; float acc=0;
        #pragma unroll 8
        for (int e=0;e<128;e++) acc=fmaf(CF[e],EX[f*132+e],acc);
        gout[(size_t)bb*128+f]=acc;
    }
}

extern "C" void kernel_launch(void* const* d_in, const int* in_sizes, int n_in,
                              void* d_out, int out_size) {
    const float* m = (const float*)d_in[0];
    const float* v = (const float*)d_in[1];
    const float* W = (const float*)d_in[2];
    const float* b = (const float*)d_in[3];
    float* out = (float*)d_out;

    vt_prep<<<1024, 128>>>(v);
    cudaFuncSetAttribute(attn_mma, cudaFuncAttributeMaxDynamicSharedMemorySize,
                         (int)SMEM_BYTES);
    attn_mma<<<1024, NT, SMEM_BYTES>>>(m, W, b, out);
}

// round 12
// speedup vs baseline: 1.0597x; 1.0597x over previous
#include <cuda_runtime.h>
#include <cuda_bf16.h>
#include <cstdint>

typedef unsigned int u32; typedef unsigned short u16;

// AttentionMV B=T=1024, E=128. mma.sync bf16 3-pass split. R12.
//  GEMM1 (per 64-t tile): D1[f][t] = sum_e WT[f][e]*m[t][e]
//  u = tanh(D1+b) -> bf16 hi/lo in registers (accum layout == B-frag layout)
//  GEMM2: pre[e][f] += sum_t vT[e][t]*u[t][f]  (reg accum over all tiles)
//  R12: tanh chunks pipelined into GEMM2, frag-packed bias, LDS.128 m-frags,
//       one barrier/tile, triple-buffered vT cp.async.

constexpr int NT = 256;
constexpr u32 WFH=0, WFL=32768;            // W frags 64KB
constexpr u32 MF0=65536, MF1=98304;        // m frag buffers (hi/lo interleaved)
constexpr u32 VTS0=131072;                 // 3 vT slots, 32KB each (hi16K+lo16K)
constexpr u32 SMEM_BYTES=229376;
// epilogue aliases (dead regions after final barrier)
constexpr u32 P_OFF=0, EX_OFF=98304, SP_OFF=188416, CF_OFF=192512;

__device__ u16 g_vtFH[131072];     // vT A-frag images, 16KB per 64-t tile
__device__ u16 g_vtFL[131072];
__device__ float g_biasF[131072];  // bias packed in accum-frag order

__device__ __forceinline__ float fast_tanh(float x){
    float e = __expf(2.0f*x);
    return 1.0f - __fdividef(2.0f, e+1.0f);
}
__device__ __forceinline__ float trunc_hi(float x){
    return __uint_as_float(__float_as_uint(x) & 0xffff0000u);
}
__device__ __forceinline__ u32 cvt_bf16x2(float hiArg, float loArg){
    u32 d; asm("cvt.rn.bf16x2.f32 %0, %1, %2;" : "=r"(d) : "f"(hiArg), "f"(loArg));
    return d;
}
__device__ __forceinline__ void mma16816(float* d, u32 a0,u32 a1,u32 a2,u32 a3,
                                         u32 b0,u32 b1){
    asm volatile("mma.sync.aligned.m16n8k16.row.col.f32.bf16.bf16.f32 "
        "{%0,%1,%2,%3}, {%4,%5,%6,%7}, {%8,%9}, {%0,%1,%2,%3};"
        : "+f"(d[0]),"+f"(d[1]),"+f"(d[2]),"+f"(d[3])
        : "r"(a0),"r"(a1),"r"(a2),"r"(a3),"r"(b0),"r"(b1));
}
__device__ __forceinline__ u32 smem_u32(const void* p){
    u32 a; asm("{ .reg .u64 t; cvta.to.shared.u64 t, %1; cvt.u32.u64 %0, t; }"
               : "=r"(a) : "l"(p));
    return a;
}
__device__ __forceinline__ void cp16(u32 dst, const void* src){
    asm volatile("cp.async.ca.shared.global [%0], [%1], 16;" :: "r"(dst), "l"(src));
}

// vT A-frag prep (verified R9/R10 layout)
__global__ void vt_prep(const float* __restrict__ gv){
    int t = blockIdx.x, e = threadIdx.x;
    float x = gv[t*128 + e];
    u16 hi = (u16)(__float_as_uint(x) >> 16);
    u16 lo = __bfloat16_as_ushort(__float2bfloat16(x - trunc_hi(x)));
    int tile = t>>6, s = (t>>4)&3, tr = t&15;
    int kh = tr>>3, rs = (tr&7)>>1, byt = tr&1;
    int i = e>>4, eq = e&15, rh = eq>>3, q = eq&7;
    int reg = rh + 2*kh, lane = q*4 + rs;
    int idx = ((tile*32 + i*4 + s)*32 + lane)*8 + reg*2 + byt;
    g_vtFH[idx] = hi; g_vtFL[idx] = lo;
}

// bias packed so the main kernel reads 8 coalesced LDG.128 per warp per tile:
// idx = (((tile*8 + w)*32 + lane)*8 + nb)*4 + c
// value = b[t][f], t = tile*64 + nb*8 + (lane&3)*2 + (c&1), f = w*16 + (lane>>2) + 8*(c>>1)
__global__ void bias_prep(const float* __restrict__ gb){
    int idx = blockIdx.x*256 + threadIdx.x;
    int c = idx&3, nb=(idx>>2)&7, lane=(idx>>5)&31, w=(idx>>10)&7, tile=idx>>13;
    int q=lane>>2, r2=(lane&3)*2;
    int t = tile*64 + nb*8 + r2 + (c&1);
    int f = w*16 + q + 8*(c>>1);
    g_biasF[idx] = gb[t*128+f];
}

__global__ __launch_bounds__(NT,1)
void attn_mma(const float* __restrict__ gm, const float* __restrict__ gW,
              float* __restrict__ gout)
{
    extern __shared__ char sm[];
    const u32 sbase = smem_u32(sm);
    const int tid=threadIdx.x, lane=tid&31, w=tid>>5, bb=blockIdx.x;
    const int q=lane>>2, r2=(lane&3)*2;
    const float* Wb = gW + (size_t)bb*16384;
    const float4* mb4 = (const float4*)(gm + (size_t)bb*131072);

    const int m_ks = lane>>2, m_r = (lane>>1)&1;
    const int m_l  = w*4 + (lane&1)*2;

    float s4[4]={0,0,0,0};
    float4 mreg[8];

    auto cpvt = [&](int tile){
        u32 dst = VTS0 + (u32)(tile%3)*32768;
        const char* srcH = (const char*)g_vtFH + (size_t)tile*16384;
        const char* srcL = (const char*)g_vtFL + (size_t)tile*16384;
        #pragma unroll
        for (int k2=0;k2<4;k2++){
            cp16(sbase + dst + tid*64 + k2*16,         srcH + tid*64 + k2*16);
            cp16(sbase + dst + 16384 + tid*64 + k2*16, srcL + tid*64 + k2*16);
        }
    };
    // m-split (verified R10 layout: [b0h,b1h,b0l,b1l] per reader-lane, ks*16 rotation)
    auto msplit = [&](u32 mf){
        #pragma unroll
        for (int j=0;j<8;j++){
            float4 x = mreg[j];
            s4[0]+=x.x; s4[1]+=x.y; s4[2]+=x.z; s4[3]+=x.w;
            u32 hA = __byte_perm(__float_as_uint(x.x), __float_as_uint(x.y), 0x7632);
            u32 hB = __byte_perm(__float_as_uint(x.z), __float_as_uint(x.w), 0x7632);
            float l0 = x.x - trunc_hi(x.x), l1 = x.y - trunc_hi(x.y);
            float l2 = x.z - trunc_hi(x.z), l3 = x.w - trunc_hi(x.w);
            u32 lA = cvt_bf16x2(l1, l0), lB = cvt_bf16x2(l3, l2);
            u32 blk = mf + (u32)(j*8 + m_ks)*512;
            u32 iA = (u32)((m_l*4     + m_r + m_ks*16) & 127);
            u32 iB = (u32)(((m_l+1)*4 + m_r + m_ks*16) & 127);
            *(u32*)(sm + blk + iA*4)     = hA;
            *(u32*)(sm + blk + iA*4 + 8) = lA;
            *(u32*)(sm + blk + iB*4)     = hB;
            *(u32*)(sm + blk + iB*4 + 8) = lB;
        }
    };

    // ---- prologue
    cpvt(0);
    asm volatile("cp.async.commit_group;");
    for (int it=0; it<64; it++){
        int idx = it*NT + tid;
        int e = idx>>7, f = idx&127;
        float x = __ldg(Wb + idx);
        u16 hi = (u16)(__float_as_uint(x) >> 16);
        u16 lo = __bfloat16_as_ushort(__float2bfloat16(x - trunc_hi(x)));
        int w2=f>>4, fr=f&15, rh=fr>>3, qq=fr&7;
        int ks=e>>4, er=e&15, kh=er>>3, rs=(er&7)>>1, byt=er&1;
        u32 off = (u32)(((w2*8+ks)*32 + qq*4 + rs)*16 + (rh + 2*kh)*4 + byt*2);
        *(u16*)(sm + WFH + off) = hi;
        *(u16*)(sm + WFL + off) = lo;
    }
    #pragma unroll
    for (int j=0;j<8;j++) mreg[j] = __ldg(mb4 + j*NT + tid);
    msplit(MF0);
    #pragma unroll
    for (int j=0;j<8;j++) mreg[j] = __ldg(mb4 + 2048 + j*NT + tid);

    float pre[8][2][4];
    #pragma unroll
    for (int i=0;i<8;i++)
        #pragma unroll
        for (int fb=0;fb<2;fb++)
            #pragma unroll
            for (int j2=0;j2<4;j2++) pre[i][fb][j2]=0.f;

    __syncthreads();   // WF + MF0 visible

    const float4* bfr = (const float4*)g_biasF;

    for (int tile=0; tile<16; tile++){
        const u32 MFp = (tile&1) ? MF1 : MF0;
        const u32 VTp = VTS0 + (u32)(tile%3)*32768;

        // bias: 8 coalesced LDG.128 (frag-packed)
        float4 bl4[8];
        #pragma unroll
        for (int nb=0;nb<8;nb++)
            bl4[nb] = __ldg(bfr + ((size_t)(tile*8+w)*32+lane)*8 + nb);

        // ---- GEMM1
        float d1[8][4];
        #pragma unroll
        for (int nb=0;nb<8;nb++){ d1[nb][0]=0;d1[nb][1]=0;d1[nb][2]=0;d1[nb][3]=0; }
        #pragma unroll
        for (int ks=0;ks<8;ks++){
            uint4 ahv = *(const uint4*)(sm + WFH + (u32)(((w*8+ks)*32+lane)*16));
            uint4 alv = *(const uint4*)(sm + WFL + (u32)(((w*8+ks)*32+lane)*16));
            uint4 bf[8];
            u32 bpos = (u32)((lane*4 + ks*16) & 127)*4;
            #pragma unroll
            for (int nb=0;nb<8;nb++)
                bf[nb] = *(const uint4*)(sm + MFp + (u32)(nb*8+ks)*512 + bpos);
            #pragma unroll
            for (int nb=0;nb<8;nb++)
                mma16816(d1[nb], ahv.x,ahv.y,ahv.z,ahv.w, bf[nb].x, bf[nb].y);
            #pragma unroll
            for (int nb=0;nb<8;nb++)
                mma16816(d1[nb], ahv.x,ahv.y,ahv.z,ahv.w, bf[nb].z, bf[nb].w);
            #pragma unroll
            for (int nb=0;nb<8;nb++)
                mma16816(d1[nb], alv.x,alv.y,alv.z,alv.w, bf[nb].x, bf[nb].y);
        }

        // ---- vT(tile+1) prefetch + next m-frags, then the single barrier
        if (tile<15) cpvt(tile+1);
        asm volatile("cp.async.commit_group;");
        if (tile<15){
            msplit((tile&1) ? MF0 : MF1);
            if (tile<14){
                #pragma unroll
                for (int j=0;j<8;j++)
                    mreg[j] = __ldg(mb4 + (tile+2)*2048 + j*NT + tid);
            }
        }
        asm volatile("cp.async.wait_group 1;");   // own vT(tile) slices done
        __syncthreads();                           // all slices + MF(next) visible

        // ---- tanh chunks pipelined into GEMM2
        u32 uh[8][2], ul[8][2];
        #pragma unroll
        for (int c=0;c<2;c++){   // chunk 0 (nb 0,1) exposed
            int nb=c;
            float u0=fast_tanh(d1[nb][0]+bl4[nb].x);
            float u1=fast_tanh(d1[nb][1]+bl4[nb].y);
            float u2=fast_tanh(d1[nb][2]+bl4[nb].z);
            float u3=fast_tanh(d1[nb][3]+bl4[nb].w);
            uh[nb][0] = __byte_perm(__float_as_uint(u0), __float_as_uint(u1), 0x7632);
            uh[nb][1] = __byte_perm(__float_as_uint(u2), __float_as_uint(u3), 0x7632);
            ul[nb][0] = cvt_bf16x2(u1 - trunc_hi(u1), u0 - trunc_hi(u0));
            ul[nb][1] = cvt_bf16x2(u3 - trunc_hi(u3), u2 - trunc_hi(u2));
        }
        #pragma unroll
        for (int s=0;s<4;s++){
            if (s<3){   // tanh for chunk s+1 hides behind this chunk's MMAs
                #pragma unroll
                for (int cc=0;cc<2;cc++){
                    int nb=2*(s+1)+cc;
                    float u0=fast_tanh(d1[nb][0]+bl4[nb].x);
                    float u1=fast_tanh(d1[nb][1]+bl4[nb].y);
                    float u2=fast_tanh(d1[nb][2]+bl4[nb].z);
                    float u3=fast_tanh(d1[nb][3]+bl4[nb].w);
                    uh[nb][0] = __byte_perm(__float_as_uint(u0), __float_as_uint(u1), 0x7632);
                    uh[nb][1] = __byte_perm(__float_as_uint(u2), __float_as_uint(u3), 0x7632);
                    ul[nb][0] = cvt_bf16x2(u1 - trunc_hi(u1), u0 - trunc_hi(u0));
                    ul[nb][1] = cvt_bf16x2(u3 - trunc_hi(u3), u2 - trunc_hi(u2));
                }
            }
            #pragma unroll
            for (int iq=0;iq<2;iq++){
                u32 ah[4][4], al[4][4];
                #pragma unroll
                for (int ii=0;ii<4;ii++){
                    int i = iq*4+ii;
                    uint4 a4 = *(const uint4*)(sm + VTp + (u32)(((i*4+s)*32+lane)*16));
                    ah[ii][0]=a4.x; ah[ii][1]=a4.y; ah[ii][2]=a4.z; ah[ii][3]=a4.w;
                    uint4 a5 = *(const uint4*)(sm + VTp + 16384 + (u32)(((i*4+s)*32+lane)*16));
                    al[ii][0]=a5.x; al[ii][1]=a5.y; al[ii][2]=a5.z; al[ii][3]=a5.w;
                }
                #pragma unroll
                for (int ii=0;ii<4;ii++)
                    #pragma unroll
                    for (int fb=0;fb<2;fb++)
                        mma16816(pre[iq*4+ii][fb], ah[ii][0],ah[ii][1],ah[ii][2],ah[ii][3],
                                 uh[2*s][fb], uh[2*s+1][fb]);
                #pragma unroll
                for (int ii=0;ii<4;ii++)
                    #pragma unroll
                    for (int fb=0;fb<2;fb++)
                        mma16816(pre[iq*4+ii][fb], ah[ii][0],ah[ii][1],ah[ii][2],ah[ii][3],
                                 ul[2*s][fb], ul[2*s+1][fb]);
                #pragma unroll
                for (int ii=0;ii<4;ii++)
                    #pragma unroll
                    for (int fb=0;fb<2;fb++)
                        mma16816(pre[iq*4+ii][fb], al[ii][0],al[ii][1],al[ii][2],al[ii][3],
                                 uh[2*s][fb], uh[2*s+1][fb]);
            }
        }
    }
    __syncthreads();   // all frag-region reads done before epilogue aliasing

    // ---- epilogue
    float* P = (float*)(sm + P_OFF);
    #pragma unroll
    for (int i=0;i<8;i++)
        #pragma unroll
        for (int fb=0;fb<2;fb++){
            int e0 = i*16+q, ff = w*16+fb*8+r2;
            P[e0*132+ff]       = pre[i][fb][0];
            P[e0*132+ff+1]     = pre[i][fb][1];
            P[(e0+8)*132+ff]   = pre[i][fb][2];
            P[(e0+8)*132+ff+1] = pre[i][fb][3];
        }
    float* SP=(float*)(sm+SP_OFF);
    *(float4*)(SP + w*128 + lane*4) = make_float4(s4[0],s4[1],s4[2],s4[3]);
    __syncthreads();

    float* EX=(float*)(sm+EX_OFF);
    float* CF=(float*)(sm+CF_OFF);
    if (tid<128){
        int e=tid;
        float ss=0;
        #pragma unroll
        for (int ww=0;ww<8;ww++) ss+=SP[ww*128+e];
        float mx=-1e30f;
        #pragma unroll 8
        for (int f=0;f<128;f++) mx=fmaxf(mx,P[e*132+f]);
        float sum=0;
        #pragma unroll 4
        for (int f=0;f<128;f++){
            float ex=__expf(P[e*132+f]-mx);
            sum+=ex; EX[f*132+e]=ex;
        }
        CF[e]=ss*__fdividef(1.f,sum);
    }
    __syncthreads();
    if (tid<128){
        int f=tid; float acc=0;
        #pragma unroll 8
        for (int e=0;e<128;e++) acc=fmaf(CF[e],EX[f*132+e],acc);
        gout[(size_t)bb*128+f]=acc;
    }
}

extern "C" void kernel_launch(void* const* d_in, const int* in_sizes, int n_in,
                              void* d_out, int out_size) {
    const float* m = (const float*)d_in[0];
    const float* v = (const float*)d_in[1];
    const float* W = (const float*)d_in[2];
    const float* b = (const float*)d_in[3];
    float* out = (float*)d_out;

    vt_prep<<<1024, 128>>>(v);
    bias_prep<<<512, 256>>>(b);
    cudaFuncSetAttribute(attn_mma, cudaFuncAttributeMaxDynamicSharedMemorySize,
                         (int)SMEM_BYTES);
    attn_mma<<<1024, NT, SMEM_BYTES>>>(m, W, out);
}